// round 15
// baseline (speedup 1.0000x reference)
#include <cuda_runtime.h>
#include <stdint.h>
#include <math.h>

// Problem constants
#define ND 4       // digits
#define NS 2048    // samples
#define NBATCH 512
#define ALPHA_C 0.1f

// scratch: n1_summed per (b,s)
__device__ int g_n1sum[NBATCH * NS];
// per-row completion counters. Never reset: each launch adds exactly 8 per
// row, so "last CTA of this launch" == (old % 8) == 7. Graph-replay safe.
__device__ unsigned g_row_done[NBATCH];

#define NEG_INF_F __uint_as_float(0xFF800000u)

// ---------------------------------------------------------------------------
// Accurate float log (musl logf, ~1 ulp) — 40 lanes per CTA, matches the
// reference's counter penalty bit-for-bit.
// ---------------------------------------------------------------------------
__device__ __forceinline__ float alogf(float x) {
    uint32_t ix = __float_as_uint(x);
    ix += 0x3f800000u - 0x3f3504f3u;
    int k = (int)(ix >> 23) - 127;
    ix = (ix & 0x007fffffu) + 0x3f3504f3u;
    float xm = __uint_as_float(ix);
    float f = xm - 1.0f;
    float s = f / (2.0f + f);
    float z = s * s;
    float w = z * z;
    float t1 = w * (0.40000972152f + w * 0.24279078841f);
    float t2 = z * (0.66666662693f + w * 0.28498786688f);
    float R = t2 + t1;
    float hfsq = 0.5f * f * f;
    float dk = (float)k;
    return s * (hfsq + R) + dk * 9.0580006145e-06f - hfsq + f
           + dk * 0.69313812256f;
}

// ---------------------------------------------------------------------------
// One category evaluation (R12 form — measured fastest): full 20-round
// threefry2x32 (c0 = 0, k1 folded into x1init by the caller), then
// u -> lg2(u)*E, index packed into the low 4 value bits. All candidates are
// <= -0.0 floats, so fmaxf on the packed float IS the argmax (FMNMX, fma
// pipe); ties resolve to the lowest category. A u==0 candidate packs to a
// NaN payload and is dropped by fmaxf — never wins, matching the reference.
// ---------------------------------------------------------------------------
__device__ __forceinline__ float cat_eval(uint32_t k0, uint32_t k1,
                                          uint32_t ks2, uint32_t x1i,
                                          float E, int cc) {
    uint32_t x0 = k0, x1 = x1i + (uint32_t)cc;
#define TF_RND(r) { x0 += x1; x1 = __funnelshift_l(x1, x1, (r)) ^ x0; }
    TF_RND(13) TF_RND(15) TF_RND(26) TF_RND(6)
    x0 += k1;  x1 += ks2 + 1u;
    TF_RND(17) TF_RND(29) TF_RND(16) TF_RND(24)
    x0 += ks2; x1 += k0 + 2u;
    TF_RND(13) TF_RND(15) TF_RND(26) TF_RND(6)
    x0 += k0;  x1 += k1 + 3u;
    TF_RND(17) TF_RND(29) TF_RND(16) TF_RND(24)
    x0 += k1;  x1 += ks2 + 4u;
    TF_RND(13) TF_RND(15) TF_RND(26) TF_RND(6)
    x0 += ks2; x1 += k0 + 5u;
#undef TF_RND
    uint32_t bits = x0 ^ x1;
    float u = __uint_as_float(0x3f800000u + __umulhi(bits, 0x00800000u)) - 1.0f;
    float lg;
    asm("lg2.approx.f32 %0, %1;" : "=f"(lg) : "f"(u));
    float v = lg * E;   // argmax lg2(u)*E; v <= -0.0
    return __uint_as_float((__float_as_uint(v) & 0xFFFFFFF0u) | (uint32_t)cc);
}

// ---------------------------------------------------------------------------
// Fused sampler + last-CTA histogram. One thread per (b, s).
//
// CODE-SIZE-MINIMIZED: digit loop (1..3) and category loop (pairs) are kept
// ROLLED so the hot body (~2 ciphers) fits in the 6KB L0 I$. The previous
// fully-unrolled body was ~80KB of SASS — past the I$ streaming plateau —
// and the issue rate was pinned at ~75% across otherwise-different variants.
// ---------------------------------------------------------------------------
__global__ void __launch_bounds__(256, 6)
sampler_kernel(const float* __restrict__ n1_logits,   // [B, D, 10]
               const float* __restrict__ counters,    // [D, 10]
               const int*   __restrict__ s_arr,       // [B]
               float* __restrict__ out,
               uint4 ka, uint4 kb) {
    __shared__ float    sE[ND * 10];  // exp(-sp)
    __shared__ int      sd[ND];       // decimal digits of s[b]
    __shared__ int      ssv;
    __shared__ uint32_t sK[2 * ND];   // per-digit threefry keys
    __shared__ int      s_last;       // am I the last CTA of this row?
    // 5120 words = 10240 packed 16-bit bins (only 10000 used); counts <=
    // 2048 so an atomicAdd of 1 or 1<<16 can never carry into the partner.
    __shared__ __align__(16) unsigned h[5120];

    const int b = blockIdx.y;
    const int t = threadIdx.x;

    if (t < ND * 10) {
        // sp computed in float EXACTLY like the reference
        float spf = n1_logits[b * (ND * 10) + t] - ALPHA_C * alogf(counters[t]);
        float e;
        float a = spf * -1.4426950408889634f;   // -sp * log2(e)
        asm("ex2.approx.f32 %0, %1;" : "=f"(e) : "f"(a));
        sE[t] = e;
    }
    if (t == 0) {
        int sv = s_arr[b];
        ssv = sv;
        sd[0] = sv / 1000;
        sd[1] = (sv / 100) % 10;
        sd[2] = (sv / 10) % 10;
        sd[3] = sv % 10;
        sK[0] = ka.x; sK[1] = ka.y; sK[2] = ka.z; sK[3] = ka.w;
        sK[4] = kb.x; sK[5] = kb.y; sK[6] = kb.z; sK[7] = kb.w;
    }
    __syncthreads();

    const int sidx = blockIdx.x * 256 + t;
    const uint32_t base = (uint32_t)(b * NS + sidx) * 10u;

    int samp[ND];

    // ---- digit 0: block-uniform bound, rolled pair loop c = 0..mx ----
    {
        const int mx = sd[0];
        const uint32_t k0 = sK[0], k1 = sK[1];
        const uint32_t ks2 = 0x1BD11BDAu ^ k0 ^ k1;
        const uint32_t bk = base + k1;
        float run = NEG_INF_F;
        int c = 0;
#pragma unroll 1
        for (; c + 1 <= mx; c += 2) {
            float p0 = cat_eval(k0, k1, ks2, bk, sE[c], c);
            float p1 = cat_eval(k0, k1, ks2, bk, sE[c + 1], c + 1);
            run = fmaxf(run, fmaxf(p0, p1));
        }
        if (c <= mx) {   // tail (always runs when mx is even, incl. mx=0)
            float p0 = cat_eval(k0, k1, ks2, bk, sE[c], c);
            run = fmaxf(run, p0);
        }
        samp[0] = (int)(__float_as_uint(run) & 15u);
    }
    int constraint = (samp[0] != sd[0]);

    // ---- digits 1..3: ROLLED digit loop + ROLLED pair loop over c ----
#pragma unroll 1
    for (int i = 1; i < ND; i++) {
        const int mx = sd[i];
        const uint32_t k0 = sK[2 * i], k1 = sK[2 * i + 1];
        const uint32_t ks2 = 0x1BD11BDAu ^ k0 ^ k1;
        const uint32_t bk = base + k1;
        const float* E = sE + i * 10;
        float pa = NEG_INF_F;   // argmax over all categories
        float pcu = NEG_INF_F;  // argmax over c <= mx
#pragma unroll 1
        for (int c = 0; c < 10; c += 2) {
            float p0 = cat_eval(k0, k1, ks2, bk, E[c], c);
            float p1 = cat_eval(k0, k1, ks2, bk, E[c + 1], c + 1);
            pa = fmaxf(pa, fmaxf(p0, p1));
            if (c <= mx) pcu = fmaxf(pcu, p0);
            if (c + 1 <= mx) pcu = fmaxf(pcu, p1);
        }
        int sm = (int)(__float_as_uint(constraint ? pa : pcu) & 15u);
        samp[i] = sm;
        constraint |= (sm != mx);
    }

    const int n1 = samp[0] * 1000 + samp[1] * 100 + samp[2] * 10 + samp[3];
    const int n2 = ssv - n1;   // in [0, 10000)

    const int lin = b * NS + sidx;
    g_n1sum[lin] = n1;

    // Output layout (float32 concat): n1_samples[B,S,D,1] | n2d[B,S,D,1] | weights[B,S]
    float4* out_n1 = (float4*)out;
    float4* out_n2 = (float4*)(out + (size_t)NBATCH * NS * ND);
    out_n1[lin] = make_float4((float)samp[0], (float)samp[1],
                              (float)samp[2], (float)samp[3]);
    // sorted-shift trick == plain decimal digits of n2
    out_n2[lin] = make_float4((float)(n2 / 1000), (float)((n2 / 100) % 10),
                              (float)((n2 / 10) % 10), (float)(n2 % 10));

    // ---- last-CTA-of-row: build this row's histogram + weights ----
    __syncthreads();   // all g_n1sum writes of this CTA are issued
    if (t == 0) {
        __threadfence();   // release our row's writes
        unsigned old = atomicAdd(&g_row_done[b], 1u);
        s_last = ((old & 7u) == 7u);
    }
    __syncthreads();
    if (!s_last) return;
    __threadfence();       // acquire the other 7 CTAs' writes

    uint4* h4 = (uint4*)h;
#pragma unroll
    for (int i = 0; i < 5; i++)
        h4[t + i * 256] = make_uint4(0, 0, 0, 0);   // 1280 uint4 == h[5120]
    __syncthreads();

    int v[NS / 256];
#pragma unroll
    for (int j = 0; j < NS / 256; j++)
        v[j] = g_n1sum[b * NS + t + j * 256];
#pragma unroll
    for (int j = 0; j < NS / 256; j++)
        atomicAdd(&h[v[j] >> 1], (v[j] & 1) ? 0x10000u : 1u);
    __syncthreads();

    float* w = out + (size_t)2 * NBATCH * NS * ND;
#pragma unroll
    for (int j = 0; j < NS / 256; j++)
        w[b * NS + t + j * 256] =
            (float)((h[v[j] >> 1] >> ((v[j] & 1) * 16)) & 0xFFFFu);
}

// ---------------------------------------------------------------------------
// Host: key derivation (threefry on CPU, deterministic, no device work)
// ---------------------------------------------------------------------------
static inline uint32_t h_rotl(uint32_t x, int r) {
    return (x << r) | (x >> (32 - r));
}
static void tf2x32_h(uint32_t k0, uint32_t k1, uint32_t c0, uint32_t c1,
                     uint32_t* o0, uint32_t* o1) {
    uint32_t ks2 = 0x1BD11BDAu ^ k0 ^ k1;
    uint32_t x0 = c0 + k0, x1 = c1 + k1;
#define TFH(r) { x0 += x1; x1 = h_rotl(x1, (r)); x1 ^= x0; }
    TFH(13) TFH(15) TFH(26) TFH(6)
    x0 += k1;  x1 += ks2 + 1u;
    TFH(17) TFH(29) TFH(16) TFH(24)
    x0 += ks2; x1 += k0 + 2u;
    TFH(13) TFH(15) TFH(26) TFH(6)
    x0 += k0;  x1 += k1 + 3u;
    TFH(17) TFH(29) TFH(16) TFH(24)
    x0 += k1;  x1 += ks2 + 4u;
    TFH(13) TFH(15) TFH(26) TFH(6)
    x0 += ks2; x1 += k0 + 5u;
#undef TFH
    *o0 = x0; *o1 = x1;
}

extern "C" void kernel_launch(void* const* d_in, const int* in_sizes, int n_in,
                              void* d_out, int out_size) {
    const float* n1_logits = (const float*)d_in[0];
    const float* counters  = (const float*)d_in[1];
    const int*   s_arr     = (const int*)d_in[2];
    float* out = (float*)d_out;

    // jax.random.key(42) -> (0, 42); 4x split (partitionable mode);
    // categorical uses the sub key.
    uint32_t kk0 = 0u, kk1 = 42u;
    uint32_t keys[8];
    for (int i = 0; i < ND; i++) {
        uint32_t nk0, nk1, sk0, sk1;
        tf2x32_h(kk0, kk1, 0u, 0u, &nk0, &nk1);
        tf2x32_h(kk0, kk1, 0u, 1u, &sk0, &sk1);
        keys[2 * i]     = sk0;
        keys[2 * i + 1] = sk1;
        kk0 = nk0; kk1 = nk1;
    }
    uint4 ka = make_uint4(keys[0], keys[1], keys[2], keys[3]);
    uint4 kb = make_uint4(keys[4], keys[5], keys[6], keys[7]);

    dim3 grid(NS / 256, NBATCH);
    sampler_kernel<<<grid, 256>>>(n1_logits, counters, s_arr, out, ka, kb);
}

// round 16
// speedup vs baseline: 1.0437x; 1.0437x over previous
#include <cuda_runtime.h>
#include <stdint.h>
#include <math.h>

// Problem constants
#define ND 4       // digits
#define NS 2048    // samples
#define NBATCH 512
#define ALPHA_C 0.1f

// scratch: n1_summed per (b,s)
__device__ int g_n1sum[NBATCH * NS];
// per-row completion counters. Never reset: each launch adds exactly 8 per
// row, so "last CTA of this launch" == (old % 8) == 7. Graph-replay safe.
__device__ unsigned g_row_done[NBATCH];

#define NEG_INF_F __uint_as_float(0xFF800000u)

// ---------------------------------------------------------------------------
// Accurate float log (musl logf, ~1 ulp) — 40 lanes per CTA, matches the
// reference's counter penalty bit-for-bit.
// ---------------------------------------------------------------------------
__device__ __forceinline__ float alogf(float x) {
    uint32_t ix = __float_as_uint(x);
    ix += 0x3f800000u - 0x3f3504f3u;
    int k = (int)(ix >> 23) - 127;
    ix = (ix & 0x007fffffu) + 0x3f3504f3u;
    float xm = __uint_as_float(ix);
    float f = xm - 1.0f;
    float s = f / (2.0f + f);
    float z = s * s;
    float w = z * z;
    float t1 = w * (0.40000972152f + w * 0.24279078841f);
    float t2 = z * (0.66666662693f + w * 0.28498786688f);
    float R = t2 + t1;
    float hfsq = 0.5f * f * f;
    float dk = (float)k;
    return s * (hfsq + R) + dk * 9.0580006145e-06f - hfsq + f
           + dk * 0.69313812256f;
}

// ---------------------------------------------------------------------------
// One category evaluation (R12 form — measured fastest): full 20-round
// threefry2x32 (c0 = 0, k1 folded into x1init by the caller), then
// u -> lg2(u)*E, index packed into the low 4 value bits. All candidates are
// <= -0.0 floats, so fmaxf on the packed float IS the argmax (FMNMX, fma
// pipe); ties resolve to the lowest category. A u==0 candidate packs to a
// NaN payload and is dropped by fmaxf — never wins, matching the reference.
// ---------------------------------------------------------------------------
__device__ __forceinline__ float cat_eval(uint32_t k0, uint32_t k1,
                                          uint32_t ks2, uint32_t x1i,
                                          float E, int cc) {
    uint32_t x0 = k0, x1 = x1i + (uint32_t)cc;
#define TF_RND(r) { x0 += x1; x1 = __funnelshift_l(x1, x1, (r)) ^ x0; }
    TF_RND(13) TF_RND(15) TF_RND(26) TF_RND(6)
    x0 += k1;  x1 += ks2 + 1u;
    TF_RND(17) TF_RND(29) TF_RND(16) TF_RND(24)
    x0 += ks2; x1 += k0 + 2u;
    TF_RND(13) TF_RND(15) TF_RND(26) TF_RND(6)
    x0 += k0;  x1 += k1 + 3u;
    TF_RND(17) TF_RND(29) TF_RND(16) TF_RND(24)
    x0 += k1;  x1 += ks2 + 4u;
    TF_RND(13) TF_RND(15) TF_RND(26) TF_RND(6)
    x0 += ks2; x1 += k0 + 5u;
#undef TF_RND
    uint32_t bits = x0 ^ x1;
    float u = __uint_as_float(0x3f800000u + __umulhi(bits, 0x00800000u)) - 1.0f;
    float lg;
    asm("lg2.approx.f32 %0, %1;" : "=f"(lg) : "f"(u));
    float v = lg * E;   // argmax lg2(u)*E; v <= -0.0
    return __uint_as_float((__float_as_uint(v) & 0xFFFFFFF0u) | (uint32_t)cc);
}

// ---------------------------------------------------------------------------
// Fused sampler + last-CTA histogram. One thread per (b, s).
//
// Code-footprint middle point (R14 was 80KB fully unrolled -> issue 74.5%;
// R15 fully rolled -> +12% insts): the DIGIT loop is rolled (3 iterations,
// ~60 overhead insts/thread) while the 10-category inner loop stays fully
// unrolled. Hot body ~14KB — L1.5-resident.
// ---------------------------------------------------------------------------
__global__ void __launch_bounds__(256, 6)
sampler_kernel(const float* __restrict__ n1_logits,   // [B, D, 10]
               const float* __restrict__ counters,    // [D, 10]
               const int*   __restrict__ s_arr,       // [B]
               float* __restrict__ out,
               uint4 ka, uint4 kb) {
    __shared__ float    sE[ND * 10];  // exp(-sp)
    __shared__ int      sd[ND];       // decimal digits of s[b]
    __shared__ int      ssv;
    __shared__ uint32_t sK[2 * ND];   // per-digit threefry keys
    __shared__ int      s_last;       // am I the last CTA of this row?
    // 5120 words = 10240 packed 16-bit bins (only 10000 used); counts <=
    // 2048 so an atomicAdd of 1 or 1<<16 can never carry into the partner.
    __shared__ __align__(16) unsigned h[5120];

    const int b = blockIdx.y;
    const int t = threadIdx.x;

    if (t < ND * 10) {
        // sp computed in float EXACTLY like the reference
        float spf = n1_logits[b * (ND * 10) + t] - ALPHA_C * alogf(counters[t]);
        float e;
        float a = spf * -1.4426950408889634f;   // -sp * log2(e)
        asm("ex2.approx.f32 %0, %1;" : "=f"(e) : "f"(a));
        sE[t] = e;
    }
    if (t == 0) {
        int sv = s_arr[b];
        ssv = sv;
        sd[0] = sv / 1000;
        sd[1] = (sv / 100) % 10;
        sd[2] = (sv / 10) % 10;
        sd[3] = sv % 10;
        sK[0] = ka.x; sK[1] = ka.y; sK[2] = ka.z; sK[3] = ka.w;
        sK[4] = kb.x; sK[5] = kb.y; sK[6] = kb.z; sK[7] = kb.w;
    }
    __syncthreads();

    const int sidx = blockIdx.x * 256 + t;
    const uint32_t base = (uint32_t)(b * NS + sidx) * 10u;

    int samp[ND];

    // ---- digit 0: block-uniform bound, pair-unrolled loop c = 0..mx ----
    {
        const int mx = sd[0];
        const uint32_t k0 = sK[0], k1 = sK[1];
        const uint32_t ks2 = 0x1BD11BDAu ^ k0 ^ k1;
        const uint32_t bk = base + k1;
        float run = NEG_INF_F;
        int c = 0;
#pragma unroll 1
        for (; c + 1 <= mx; c += 2) {
            float p0 = cat_eval(k0, k1, ks2, bk, sE[c], c);
            float p1 = cat_eval(k0, k1, ks2, bk, sE[c + 1], c + 1);
            run = fmaxf(run, fmaxf(p0, p1));
        }
        if (c <= mx) {   // tail (always runs when mx is even, incl. mx=0)
            float p0 = cat_eval(k0, k1, ks2, bk, sE[c], c);
            run = fmaxf(run, p0);
        }
        samp[0] = (int)(__float_as_uint(run) & 15u);
    }
    int constraint = (samp[0] != sd[0]);

    // ---- digits 1..3: ROLLED digit loop, UNROLLED 10-category body ----
#pragma unroll 1
    for (int i = 1; i < ND; i++) {
        const int mx = sd[i];
        const uint32_t k0 = sK[2 * i], k1 = sK[2 * i + 1];
        const uint32_t ks2 = 0x1BD11BDAu ^ k0 ^ k1;
        const uint32_t bk = base + k1;
        const float* E = sE + i * 10;
        float pa = NEG_INF_F;   // argmax over all categories
        float pcu = NEG_INF_F;  // argmax over c <= mx
#pragma unroll
        for (int c = 0; c < 10; c++) {
            float p = cat_eval(k0, k1, ks2, bk, E[c], c);
            pa = fmaxf(pa, p);
            if (c <= mx) pcu = fmaxf(pcu, p);
        }
        int sm = (int)(__float_as_uint(constraint ? pa : pcu) & 15u);
        samp[i] = sm;
        constraint |= (sm != mx);
    }

    const int n1 = samp[0] * 1000 + samp[1] * 100 + samp[2] * 10 + samp[3];
    const int n2 = ssv - n1;   // in [0, 10000)

    const int lin = b * NS + sidx;
    g_n1sum[lin] = n1;

    // Output layout (float32 concat): n1_samples[B,S,D,1] | n2d[B,S,D,1] | weights[B,S]
    float4* out_n1 = (float4*)out;
    float4* out_n2 = (float4*)(out + (size_t)NBATCH * NS * ND);
    out_n1[lin] = make_float4((float)samp[0], (float)samp[1],
                              (float)samp[2], (float)samp[3]);
    // sorted-shift trick == plain decimal digits of n2
    out_n2[lin] = make_float4((float)(n2 / 1000), (float)((n2 / 100) % 10),
                              (float)((n2 / 10) % 10), (float)(n2 % 10));

    // ---- last-CTA-of-row: build this row's histogram + weights ----
    __syncthreads();   // all g_n1sum writes of this CTA are issued
    if (t == 0) {
        __threadfence();   // release our row's writes
        unsigned old = atomicAdd(&g_row_done[b], 1u);
        s_last = ((old & 7u) == 7u);
    }
    __syncthreads();
    if (!s_last) return;
    __threadfence();       // acquire the other 7 CTAs' writes

    uint4* h4 = (uint4*)h;
#pragma unroll
    for (int i = 0; i < 5; i++)
        h4[t + i * 256] = make_uint4(0, 0, 0, 0);   // 1280 uint4 == h[5120]
    __syncthreads();

    int v[NS / 256];
#pragma unroll
    for (int j = 0; j < NS / 256; j++)
        v[j] = g_n1sum[b * NS + t + j * 256];
#pragma unroll
    for (int j = 0; j < NS / 256; j++)
        atomicAdd(&h[v[j] >> 1], (v[j] & 1) ? 0x10000u : 1u);
    __syncthreads();

    float* w = out + (size_t)2 * NBATCH * NS * ND;
#pragma unroll
    for (int j = 0; j < NS / 256; j++)
        w[b * NS + t + j * 256] =
            (float)((h[v[j] >> 1] >> ((v[j] & 1) * 16)) & 0xFFFFu);
}

// ---------------------------------------------------------------------------
// Host: key derivation (threefry on CPU, deterministic, no device work)
// ---------------------------------------------------------------------------
static inline uint32_t h_rotl(uint32_t x, int r) {
    return (x << r) | (x >> (32 - r));
}
static void tf2x32_h(uint32_t k0, uint32_t k1, uint32_t c0, uint32_t c1,
                     uint32_t* o0, uint32_t* o1) {
    uint32_t ks2 = 0x1BD11BDAu ^ k0 ^ k1;
    uint32_t x0 = c0 + k0, x1 = c1 + k1;
#define TFH(r) { x0 += x1; x1 = h_rotl(x1, (r)); x1 ^= x0; }
    TFH(13) TFH(15) TFH(26) TFH(6)
    x0 += k1;  x1 += ks2 + 1u;
    TFH(17) TFH(29) TFH(16) TFH(24)
    x0 += ks2; x1 += k0 + 2u;
    TFH(13) TFH(15) TFH(26) TFH(6)
    x0 += k0;  x1 += k1 + 3u;
    TFH(17) TFH(29) TFH(16) TFH(24)
    x0 += k1;  x1 += ks2 + 4u;
    TFH(13) TFH(15) TFH(26) TFH(6)
    x0 += ks2; x1 += k0 + 5u;
#undef TFH
    *o0 = x0; *o1 = x1;
}

extern "C" void kernel_launch(void* const* d_in, const int* in_sizes, int n_in,
                              void* d_out, int out_size) {
    const float* n1_logits = (const float*)d_in[0];
    const float* counters  = (const float*)d_in[1];
    const int*   s_arr     = (const int*)d_in[2];
    float* out = (float*)d_out;

    // jax.random.key(42) -> (0, 42); 4x split (partitionable mode);
    // categorical uses the sub key.
    uint32_t kk0 = 0u, kk1 = 42u;
    uint32_t keys[8];
    for (int i = 0; i < ND; i++) {
        uint32_t nk0, nk1, sk0, sk1;
        tf2x32_h(kk0, kk1, 0u, 0u, &nk0, &nk1);
        tf2x32_h(kk0, kk1, 0u, 1u, &sk0, &sk1);
        keys[2 * i]     = sk0;
        keys[2 * i + 1] = sk1;
        kk0 = nk0; kk1 = nk1;
    }
    uint4 ka = make_uint4(keys[0], keys[1], keys[2], keys[3]);
    uint4 kb = make_uint4(keys[4], keys[5], keys[6], keys[7]);

    dim3 grid(NS / 256, NBATCH);
    sampler_kernel<<<grid, 256>>>(n1_logits, counters, s_arr, out, ka, kb);
}

// round 17
// speedup vs baseline: 1.0679x; 1.0232x over previous
#include <cuda_runtime.h>
#include <stdint.h>
#include <math.h>

// Problem constants
#define ND 4       // digits
#define NS 2048    // samples
#define NBATCH 512
#define ALPHA_C 0.1f

// scratch: n1_summed per (b,s)
__device__ int g_n1sum[NBATCH * NS];
// per-row completion counters. Never reset: each launch adds exactly 8 per
// row, so "last CTA of this launch" == (old % 8) == 7. Graph-replay safe.
__device__ unsigned g_row_done[NBATCH];

#define NEG_INF_F __uint_as_float(0xFF800000u)

// ---------------------------------------------------------------------------
// Accurate float log (musl logf, ~1 ulp) — 40 lanes per CTA, matches the
// reference's counter penalty bit-for-bit.
// ---------------------------------------------------------------------------
__device__ __forceinline__ float alogf(float x) {
    uint32_t ix = __float_as_uint(x);
    ix += 0x3f800000u - 0x3f3504f3u;
    int k = (int)(ix >> 23) - 127;
    ix = (ix & 0x007fffffu) + 0x3f3504f3u;
    float xm = __uint_as_float(ix);
    float f = xm - 1.0f;
    float s = f / (2.0f + f);
    float z = s * s;
    float w = z * z;
    float t1 = w * (0.40000972152f + w * 0.24279078841f);
    float t2 = z * (0.66666662693f + w * 0.28498786688f);
    float R = t2 + t1;
    float hfsq = 0.5f * f * f;
    float dk = (float)k;
    return s * (hfsq + R) + dk * 9.0580006145e-06f - hfsq + f
           + dk * 0.69313812256f;
}

// ---------------------------------------------------------------------------
// One category evaluation (R12 form — measured fastest): full 20-round
// threefry2x32 (c0 = 0, k1 folded into x1init by the caller), then
// u -> lg2(u)*E, index packed into the low 4 value bits. All candidates are
// <= -0.0 floats, so fmaxf on the packed float IS the argmax (FMNMX); ties
// resolve to the lowest category. A u==0 candidate packs to a NaN payload
// and is dropped by fmaxf — never wins, matching the reference's clamp.
// ---------------------------------------------------------------------------
__device__ __forceinline__ float cat_eval(uint32_t k0, uint32_t k1,
                                          uint32_t ks2, uint32_t x1i,
                                          float E, int cc) {
    uint32_t x0 = k0, x1 = x1i + (uint32_t)cc;
#define TF_RND(r) { x0 += x1; x1 = __funnelshift_l(x1, x1, (r)) ^ x0; }
    TF_RND(13) TF_RND(15) TF_RND(26) TF_RND(6)
    x0 += k1;  x1 += ks2 + 1u;
    TF_RND(17) TF_RND(29) TF_RND(16) TF_RND(24)
    x0 += ks2; x1 += k0 + 2u;
    TF_RND(13) TF_RND(15) TF_RND(26) TF_RND(6)
    x0 += k0;  x1 += k1 + 3u;
    TF_RND(17) TF_RND(29) TF_RND(16) TF_RND(24)
    x0 += k1;  x1 += ks2 + 4u;
    TF_RND(13) TF_RND(15) TF_RND(26) TF_RND(6)
    x0 += ks2; x1 += k0 + 5u;
#undef TF_RND
    uint32_t bits = x0 ^ x1;
    float u = __uint_as_float(0x3f800000u + __umulhi(bits, 0x00800000u)) - 1.0f;
    float lg;
    asm("lg2.approx.f32 %0, %1;" : "=f"(lg) : "f"(u));
    float v = lg * E;   // argmax lg2(u)*E; v <= -0.0
    return __uint_as_float((__float_as_uint(v) & 0xFFFFFFF0u) | (uint32_t)cc);
}

// ---------------------------------------------------------------------------
// Fused sampler + last-CTA histogram. One thread per (b, s).
// R12 structure (full unroll digits 1-3 — fastest measured) with R14's
// 16-bit packed histogram (21KB smem) and regs<=40 via launch_bounds.
// New: digit-0 mx==0 -> samp[0]=0 without any cipher (argmax over a single
// category; per-(s,c) counters mean no draw-position shift). Block-uniform.
// ---------------------------------------------------------------------------
__global__ void __launch_bounds__(256, 6)
sampler_kernel(const float* __restrict__ n1_logits,   // [B, D, 10]
               const float* __restrict__ counters,    // [D, 10]
               const int*   __restrict__ s_arr,       // [B]
               float* __restrict__ out,
               uint4 ka, uint4 kb) {
    __shared__ float    sE[ND * 10];  // exp(-sp)
    __shared__ int      sd[ND];       // decimal digits of s[b]
    __shared__ int      ssv;
    __shared__ uint32_t sK[2 * ND];   // per-digit threefry keys
    __shared__ int      s_last;       // am I the last CTA of this row?
    // 5120 words = 10240 packed 16-bit bins (only 10000 used); counts <=
    // 2048 so an atomicAdd of 1 or 1<<16 can never carry into the partner.
    __shared__ __align__(16) unsigned h[5120];

    const int b = blockIdx.y;
    const int t = threadIdx.x;

    if (t < ND * 10) {
        // sp computed in float EXACTLY like the reference
        float spf = n1_logits[b * (ND * 10) + t] - ALPHA_C * alogf(counters[t]);
        float e;
        float a = spf * -1.4426950408889634f;   // -sp * log2(e)
        asm("ex2.approx.f32 %0, %1;" : "=f"(e) : "f"(a));
        sE[t] = e;
    }
    if (t == 0) {
        int sv = s_arr[b];
        ssv = sv;
        sd[0] = sv / 1000;
        sd[1] = (sv / 100) % 10;
        sd[2] = (sv / 10) % 10;
        sd[3] = sv % 10;
        sK[0] = ka.x; sK[1] = ka.y; sK[2] = ka.z; sK[3] = ka.w;
        sK[4] = kb.x; sK[5] = kb.y; sK[6] = kb.z; sK[7] = kb.w;
    }
    __syncthreads();

    const int sidx = blockIdx.x * 256 + t;
    const uint32_t base = (uint32_t)(b * NS + sidx) * 10u;

    int samp[ND];

    // ---- digit 0: block-uniform bound; mx==0 needs NO cipher ----
    {
        const int mx = sd[0];
        if (mx == 0) {
            samp[0] = 0;
        } else {
            const uint32_t k0 = sK[0], k1 = sK[1];
            const uint32_t ks2 = 0x1BD11BDAu ^ k0 ^ k1;
            const uint32_t bk = base + k1;
            float run = NEG_INF_F;
            int c = 0;
#pragma unroll 1
            for (; c + 1 <= mx; c += 2) {
                float p0 = cat_eval(k0, k1, ks2, bk, sE[c], c);
                float p1 = cat_eval(k0, k1, ks2, bk, sE[c + 1], c + 1);
                run = fmaxf(run, fmaxf(p0, p1));
            }
            if (c <= mx) {   // tail when mx is even
                float p0 = cat_eval(k0, k1, ks2, bk, sE[c], c);
                run = fmaxf(run, p0);
            }
            samp[0] = (int)(__float_as_uint(run) & 15u);
        }
    }
    int constraint = (samp[0] != sd[0]);

    // ---- digits 1..3: FULLY UNROLLED, all 10 categories, dual argmax ----
#pragma unroll
    for (int i = 1; i < ND; i++) {
        const int mx = sd[i];
        const uint32_t k0 = sK[2 * i], k1 = sK[2 * i + 1];
        const uint32_t ks2 = 0x1BD11BDAu ^ k0 ^ k1;
        const uint32_t bk = base + k1;
        const float* E = sE + i * 10;
        float p[10];
#pragma unroll
        for (int c = 0; c < 10; c++)
            p[c] = cat_eval(k0, k1, ks2, bk, E[c], c);
        // pairwise tree for the full-range argmax (shorter dep chain)
        float m01 = fmaxf(p[0], p[1]), m23 = fmaxf(p[2], p[3]);
        float m45 = fmaxf(p[4], p[5]), m67 = fmaxf(p[6], p[7]);
        float m89 = fmaxf(p[8], p[9]);
        float pa = fmaxf(fmaxf(fmaxf(m01, m23), fmaxf(m45, m67)), m89);
        // prefix argmax over c <= mx (sequential, predicated)
        float pcu = p[0];
#pragma unroll
        for (int c = 1; c < 10; c++)
            if (c <= mx) pcu = fmaxf(pcu, p[c]);
        int sm = (int)(__float_as_uint(constraint ? pa : pcu) & 15u);
        samp[i] = sm;
        constraint |= (sm != mx);
    }

    const int n1 = samp[0] * 1000 + samp[1] * 100 + samp[2] * 10 + samp[3];
    const int n2 = ssv - n1;   // in [0, 10000)

    const int lin = b * NS + sidx;
    g_n1sum[lin] = n1;

    // Output layout (float32 concat): n1_samples[B,S,D,1] | n2d[B,S,D,1] | weights[B,S]
    float4* out_n1 = (float4*)out;
    float4* out_n2 = (float4*)(out + (size_t)NBATCH * NS * ND);
    out_n1[lin] = make_float4((float)samp[0], (float)samp[1],
                              (float)samp[2], (float)samp[3]);
    // sorted-shift trick == plain decimal digits of n2
    out_n2[lin] = make_float4((float)(n2 / 1000), (float)((n2 / 100) % 10),
                              (float)((n2 / 10) % 10), (float)(n2 % 10));

    // ---- last-CTA-of-row: build this row's histogram + weights ----
    __syncthreads();   // all g_n1sum writes of this CTA are issued
    if (t == 0) {
        __threadfence();   // release our row's writes
        unsigned old = atomicAdd(&g_row_done[b], 1u);
        s_last = ((old & 7u) == 7u);
    }
    __syncthreads();
    if (!s_last) return;
    __threadfence();       // acquire the other 7 CTAs' writes

    uint4* h4 = (uint4*)h;
#pragma unroll
    for (int i = 0; i < 5; i++)
        h4[t + i * 256] = make_uint4(0, 0, 0, 0);   // 1280 uint4 == h[5120]
    __syncthreads();

    int v[NS / 256];
#pragma unroll
    for (int j = 0; j < NS / 256; j++)
        v[j] = g_n1sum[b * NS + t + j * 256];
#pragma unroll
    for (int j = 0; j < NS / 256; j++)
        atomicAdd(&h[v[j] >> 1], (v[j] & 1) ? 0x10000u : 1u);
    __syncthreads();

    float* w = out + (size_t)2 * NBATCH * NS * ND;
#pragma unroll
    for (int j = 0; j < NS / 256; j++)
        w[b * NS + t + j * 256] =
            (float)((h[v[j] >> 1] >> ((v[j] & 1) * 16)) & 0xFFFFu);
}

// ---------------------------------------------------------------------------
// Host: key derivation (threefry on CPU, deterministic, no device work)
// ---------------------------------------------------------------------------
static inline uint32_t h_rotl(uint32_t x, int r) {
    return (x << r) | (x >> (32 - r));
}
static void tf2x32_h(uint32_t k0, uint32_t k1, uint32_t c0, uint32_t c1,
                     uint32_t* o0, uint32_t* o1) {
    uint32_t ks2 = 0x1BD11BDAu ^ k0 ^ k1;
    uint32_t x0 = c0 + k0, x1 = c1 + k1;
#define TFH(r) { x0 += x1; x1 = h_rotl(x1, (r)); x1 ^= x0; }
    TFH(13) TFH(15) TFH(26) TFH(6)
    x0 += k1;  x1 += ks2 + 1u;
    TFH(17) TFH(29) TFH(16) TFH(24)
    x0 += ks2; x1 += k0 + 2u;
    TFH(13) TFH(15) TFH(26) TFH(6)
    x0 += k0;  x1 += k1 + 3u;
    TFH(17) TFH(29) TFH(16) TFH(24)
    x0 += k1;  x1 += ks2 + 4u;
    TFH(13) TFH(15) TFH(26) TFH(6)
    x0 += ks2; x1 += k0 + 5u;
#undef TFH
    *o0 = x0; *o1 = x1;
}

extern "C" void kernel_launch(void* const* d_in, const int* in_sizes, int n_in,
                              void* d_out, int out_size) {
    const float* n1_logits = (const float*)d_in[0];
    const float* counters  = (const float*)d_in[1];
    const int*   s_arr     = (const int*)d_in[2];
    float* out = (float*)d_out;

    // jax.random.key(42) -> (0, 42); 4x split (partitionable mode);
    // categorical uses the sub key.
    uint32_t kk0 = 0u, kk1 = 42u;
    uint32_t keys[8];
    for (int i = 0; i < ND; i++) {
        uint32_t nk0, nk1, sk0, sk1;
        tf2x32_h(kk0, kk1, 0u, 0u, &nk0, &nk1);
        tf2x32_h(kk0, kk1, 0u, 1u, &sk0, &sk1);
        keys[2 * i]     = sk0;
        keys[2 * i + 1] = sk1;
        kk0 = nk0; kk1 = nk1;
    }
    uint4 ka = make_uint4(keys[0], keys[1], keys[2], keys[3]);
    uint4 kb = make_uint4(keys[4], keys[5], keys[6], keys[7]);

    dim3 grid(NS / 256, NBATCH);
    sampler_kernel<<<grid, 256>>>(n1_logits, counters, s_arr, out, ka, kb);
}